// round 15
// baseline (speedup 1.0000x reference)
#include <cuda_runtime.h>
#include <cuda_fp16.h>
#include <math.h>
#include <float.h>

#define NB    64
#define NGPB  2000
#define EGPB  64000
#define NN    (NB*NGPB)     // 128000 nodes
#define NE    (NB*EGPB)     // 4096000 edges
#define KSEL  1600
#define EMB   64
#define G1    32
#define G2    32
#define DENSE 64
#define NCLS  10
#define FEAT  10000
#define CAP   80            // padded CSR bucket capacity (deg max ~62; round8+16 = 80 fits)
#define QTR   500           // dst nodes owned per build-CTA (4 CTAs per batch)
#define ZROW  NGPB          // local zero-row id (smem row 2000)
#define AGG_T 768           // agg threads (24 warps; raises reg ceiling to 85)

// dynamic smem for agg: (NGPB+1) rows x 64 B
#define AGG_SMEM ((NGPB + 1) * 64)

// ---------------- scratch (static device globals; no runtime alloc) ----------
__device__ int     g_cnt[NN];           // per-node in-degree
__device__ float   g_dinv[NN];
__device__ int     g_csrc[NN*CAP];      // padded CSR of LOCAL src ids; pad = ZROW
__device__ float   g_embW1[FEAT*G1];    // emb @ W1  (10000 x 32)
__device__ __half2 g_hs16 [NN*16];      // layer-1 input fp16 (pre-scaled by dinv[src])
__device__ __half2 g_hs216[NN*16];      // layer-2 input fp16 (pre-scaled)
__device__ float   g_h2 [NN*G2];        // final node features (fp32)
__device__ float   g_score[NN];

// ---------------- emb @ W1 (tiny table GEMM) ---------------------------------
__global__ void k_embW1(const float* __restrict__ emb, const float* __restrict__ W1) {
    __shared__ float W1s[EMB*G1];
    for (int i = threadIdx.x; i < EMB*G1; i += blockDim.x) W1s[i] = W1[i];
    __syncthreads();
    int warp = threadIdx.x >> 5, lane = threadIdx.x & 31;
    int r = blockIdx.x*8 + warp;
    if (r >= FEAT) return;
    float e0 = emb[r*EMB + lane];
    float e1 = emb[r*EMB + 32 + lane];
    float acc = 0.f;
    #pragma unroll
    for (int k = 0; k < 32; k++)
        acc += __shfl_sync(0xffffffffu, e0, k) * W1s[k*G1 + lane];
    #pragma unroll
    for (int k = 0; k < 32; k++)
        acc += __shfl_sync(0xffffffffu, e1, k) * W1s[(32+k)*G1 + lane];
    g_embW1[r*G1 + lane] = acc;
}

// ---------------- CSR build: smem counters + direct gmem scatter -------------
// 4 CTAs per batch; CTA owns dst range [b*NGPB + q*QTR, +QTR). Stores LOCAL
// src ids (src - b*NGPB); pad entries = ZROW (smem zero row in agg).
// Pad window covers the 8-edge unrolled agg loop: [c, round8(c)+16) <= CAP.
__global__ void __launch_bounds__(1024) k_build(const int* __restrict__ ei,
                                                const int* __restrict__ x) {
    __shared__ int scnt[QTR];
    int b = blockIdx.x >> 2, q = blockIdx.x & 3;
    int tid = threadIdx.x;
    for (int i = tid; i < QTR; i += 1024) scnt[i] = 0;
    __syncthreads();
    int ebase = b*EGPB;
    int bbase = b*NGPB;
    int lo    = bbase + q*QTR;
    const int4* __restrict__ s4 = (const int4*)(ei + ebase);
    const int4* __restrict__ d4 = (const int4*)(ei + NE + ebase);
    for (int t = tid; t < EGPB/4; t += 1024) {
        int4 d = d4[t];
        int4 s = s4[t];
        unsigned r;
        r = (unsigned)(d.x - lo);
        if (r < QTR) g_csrc[d.x*CAP + atomicAdd(&scnt[r], 1)] = s.x - bbase;
        r = (unsigned)(d.y - lo);
        if (r < QTR) g_csrc[d.y*CAP + atomicAdd(&scnt[r], 1)] = s.y - bbase;
        r = (unsigned)(d.z - lo);
        if (r < QTR) g_csrc[d.z*CAP + atomicAdd(&scnt[r], 1)] = s.z - bbase;
        r = (unsigned)(d.w - lo);
        if (r < QTR) g_csrc[d.w*CAP + atomicAdd(&scnt[r], 1)] = s.w - bbase;
    }
    __syncthreads();
    // cnt, dinv, tail pads, hs (fp16) for owned nodes (warp per node)
    int warp = tid >> 5, lane = tid & 31;
    for (int i = warp; i < QTR; i += 32) {
        int v = lo + i;
        int c = scnt[i];
        float dinv = rsqrtf((float)(c + 1));      // +1 self loop
        if (lane == 0) { g_cnt[v] = c; g_dinv[v] = dinv; }
        int padend = ((c + 7) & ~7) + 16;         // covers 8-edge tail + prefetch
        if (padend > CAP) padend = CAP;
        int p = c + lane;
        if (p < padend) g_csrc[v*CAP + p] = ZROW; // max pad span 23 < 32 lanes
        int row = x[v];
        if (lane < 16) {
            float2 e = *(const float2*)&g_embW1[row*32 + 2*lane];
            g_hs16[v*16 + lane] = __floats2half2_rn(e.x*dinv, e.y*dinv);
        }
    }
}

// ---------------- GCN aggregation: SMEM-staged batch block -------------------
// 2 CTAs per batch (128 CTAs, 768 thr = 24 warps, 1 CTA/SM). Batch feature
// block (2000 x 64 B fp16 rows + zero row) staged in dynamic smem. 4-lane
// group per dst node. 8-edge inner loop: two prefetched index quads, all 8
// LDS.128 gathers in flight, fp16 hadd2 trees, promote to fp32 per quad.
__device__ __forceinline__ __half2 h2u(unsigned u) { return *(__half2*)&u; }

__device__ __forceinline__ void accum8(float* a, uint4 r) {
    float2 t;
    t = __half22float2(h2u(r.x)); a[0] += t.x; a[1] += t.y;
    t = __half22float2(h2u(r.y)); a[2] += t.x; a[3] += t.y;
    t = __half22float2(h2u(r.z)); a[4] += t.x; a[5] += t.y;
    t = __half22float2(h2u(r.w)); a[6] += t.x; a[7] += t.y;
}

template<int MODE>
__global__ void __launch_bounds__(AGG_T) k_agg(const float* __restrict__ bias,
                                               const float* __restrict__ W2,
                                               const float* __restrict__ pw) {
    extern __shared__ uint4 sblk[];         // (NGPB+1) rows x 4 uint4
    __shared__ float W2s[G2*G2];
    int tid = threadIdx.x;
    if (MODE == 1)
        for (int i = tid; i < G2*G2; i += AGG_T) W2s[i] = W2[i];
    int b = blockIdx.x >> 1, half = blockIdx.x & 1;
    const uint4* __restrict__ gin =
        (const uint4*)((MODE == 1) ? g_hs16 : g_hs216);
    // stage batch block (coalesced) + zero row
    for (int i = tid; i < NGPB*4; i += AGG_T) sblk[i] = gin[b*NGPB*4 + i];
    if (tid < 4) sblk[NGPB*4 + tid] = make_uint4(0u, 0u, 0u, 0u);
    __syncthreads();

    int lane = tid & 31, warp = tid >> 5;
    int g = lane & 3;                         // lane within 4-lane group
    for (int o = warp; o < 125; o += 24) {    // 125*8 = 1000 nodes per CTA
        int vl = half*1000 + o*8 + (lane >> 2);   // local node id in batch
        int v  = b*NGPB + vl;
        int dg = g_cnt[v];
        float dinv = g_dinv[v];
        const int* __restrict__ bucket = g_csrc + v*CAP;   // local ids

        float a[8] = {0,0,0,0,0,0,0,0};
        accum8(a, sblk[vl*4 + g]);            // self loop
        int4 iA = *(const int4*)(bucket);     // first two index quads
        int4 iB = *(const int4*)(bucket + 4);
        for (int j = 0; j < dg; j += 8) {     // pads index the zero row
            int4 cA = iA, cB = iB;
            iA = *(const int4*)(bucket + j + 8);    // prefetch next pair
            iB = *(const int4*)(bucket + j + 12);
            uint4 r0 = sblk[cA.x*4 + g];
            uint4 r1 = sblk[cA.y*4 + g];
            uint4 r2 = sblk[cA.z*4 + g];
            uint4 r3 = sblk[cA.w*4 + g];
            uint4 r4 = sblk[cB.x*4 + g];
            uint4 r5 = sblk[cB.y*4 + g];
            uint4 r6 = sblk[cB.z*4 + g];
            uint4 r7 = sblk[cB.w*4 + g];
            __half2 q0 = __hadd2(__hadd2(h2u(r0.x), h2u(r1.x)), __hadd2(h2u(r2.x), h2u(r3.x)));
            __half2 q1 = __hadd2(__hadd2(h2u(r0.y), h2u(r1.y)), __hadd2(h2u(r2.y), h2u(r3.y)));
            __half2 q2 = __hadd2(__hadd2(h2u(r0.z), h2u(r1.z)), __hadd2(h2u(r2.z), h2u(r3.z)));
            __half2 q3 = __hadd2(__hadd2(h2u(r0.w), h2u(r1.w)), __hadd2(h2u(r2.w), h2u(r3.w)));
            float2 t;
            t = __half22float2(q0); a[0] += t.x; a[1] += t.y;
            t = __half22float2(q1); a[2] += t.x; a[3] += t.y;
            t = __half22float2(q2); a[4] += t.x; a[5] += t.y;
            t = __half22float2(q3); a[6] += t.x; a[7] += t.y;
            __half2 p0 = __hadd2(__hadd2(h2u(r4.x), h2u(r5.x)), __hadd2(h2u(r6.x), h2u(r7.x)));
            __half2 p1 = __hadd2(__hadd2(h2u(r4.y), h2u(r5.y)), __hadd2(h2u(r6.y), h2u(r7.y)));
            __half2 p2 = __hadd2(__hadd2(h2u(r4.z), h2u(r5.z)), __hadd2(h2u(r6.z), h2u(r7.z)));
            __half2 p3 = __hadd2(__hadd2(h2u(r4.w), h2u(r5.w)), __hadd2(h2u(r6.w), h2u(r7.w)));
            t = __half22float2(p0); a[0] += t.x; a[1] += t.y;
            t = __half22float2(p1); a[2] += t.x; a[3] += t.y;
            t = __half22float2(p2); a[4] += t.x; a[5] += t.y;
            t = __half22float2(p3); a[6] += t.x; a[7] += t.y;
        }
        float4 bs0 = *(const float4*)(bias + g*8);
        float4 bs1 = *(const float4*)(bias + g*8 + 4);
        float vals[8];
        vals[0] = fmaxf(dinv*a[0] + bs0.x, 0.f);
        vals[1] = fmaxf(dinv*a[1] + bs0.y, 0.f);
        vals[2] = fmaxf(dinv*a[2] + bs0.z, 0.f);
        vals[3] = fmaxf(dinv*a[3] + bs0.w, 0.f);
        vals[4] = fmaxf(dinv*a[4] + bs1.x, 0.f);
        vals[5] = fmaxf(dinv*a[5] + bs1.y, 0.f);
        vals[6] = fmaxf(dinv*a[6] + bs1.z, 0.f);
        vals[7] = fmaxf(dinv*a[7] + bs1.w, 0.f);

        if (MODE == 1) {
            // hs2[v][c] = dinv * sum_k val_k W2[k][c], c = g*8..g*8+7 (fp16)
            float acc[8] = {0,0,0,0,0,0,0,0};
            int base = lane & ~3;
            #pragma unroll
            for (int kl = 0; kl < 4; kl++) {
                #pragma unroll
                for (int i = 0; i < 8; i++) {
                    float vx = __shfl_sync(0xffffffffu, vals[i], base + kl);
                    int k = kl*8 + i;
                    float4 w0 = *(const float4*)&W2s[k*G2 + g*8];
                    float4 w1 = *(const float4*)&W2s[k*G2 + g*8 + 4];
                    acc[0] += vx*w0.x; acc[1] += vx*w0.y;
                    acc[2] += vx*w0.z; acc[3] += vx*w0.w;
                    acc[4] += vx*w1.x; acc[5] += vx*w1.y;
                    acc[6] += vx*w1.z; acc[7] += vx*w1.w;
                }
            }
            __half2 h0 = __floats2half2_rn(acc[0]*dinv, acc[1]*dinv);
            __half2 h1 = __floats2half2_rn(acc[2]*dinv, acc[3]*dinv);
            __half2 h2 = __floats2half2_rn(acc[4]*dinv, acc[5]*dinv);
            __half2 h3 = __floats2half2_rn(acc[6]*dinv, acc[7]*dinv);
            uint4 ov;
            ov.x = *(unsigned*)&h0; ov.y = *(unsigned*)&h1;
            ov.z = *(unsigned*)&h2; ov.w = *(unsigned*)&h3;
            ((uint4*)g_hs216)[v*4 + g] = ov;
        } else {
            *(float4*)(g_h2 + v*32 + g*8)     = make_float4(vals[0], vals[1], vals[2], vals[3]);
            *(float4*)(g_h2 + v*32 + g*8 + 4) = make_float4(vals[4], vals[5], vals[6], vals[7]);
            float4 p0 = *(const float4*)(pw + g*8);
            float4 p1 = *(const float4*)(pw + g*8 + 4);
            float dot = vals[0]*p0.x + vals[1]*p0.y + vals[2]*p0.z + vals[3]*p0.w
                      + vals[4]*p1.x + vals[5]*p1.y + vals[6]*p1.z + vals[7]*p1.w;
            float nrm = p0.x*p0.x + p0.y*p0.y + p0.z*p0.z + p0.w*p0.w
                      + p1.x*p1.x + p1.y*p1.y + p1.z*p1.z + p1.w*p1.w;
            #pragma unroll
            for (int o2 = 1; o2 < 4; o2 <<= 1) {
                dot += __shfl_xor_sync(0xffffffffu, dot, o2);
                nrm += __shfl_xor_sync(0xffffffffu, nrm, o2);
            }
            if (g == 0) g_score[v] = tanhf(dot * rsqrtf(nrm));
        }
    }
}

// ---------------- top-k (exact radix select) + pool + dense head -------------
__device__ __forceinline__ unsigned key_flip(unsigned u) {
    return (u & 0x80000000u) ? ~u : (u | 0x80000000u);   // monotone float order
}

__global__ void __launch_bounds__(1024) k_topk(
        const float* __restrict__ dense_W, const float* __restrict__ dense_b,
        const float* __restrict__ out_W,  const float* __restrict__ out_b,
        float* __restrict__ out) {
    __shared__ unsigned keys[NGPB];
    __shared__ int      hist[256];
    __shared__ int      sh_byte, sh_rem;
    __shared__ float    red[32*32];
    __shared__ float    gvec[G2];
    __shared__ float    dvec[DENSE];
    int b = blockIdx.x, tid = threadIdx.x;
    for (int i = tid; i < NGPB; i += 1024)
        keys[i] = key_flip(__float_as_uint(g_score[b*NGPB + i]));
    __syncthreads();

    // exact KSEL-th largest key via 4 byte-wise passes
    unsigned prefix = 0;
    int remaining = KSEL;
    #pragma unroll
    for (int s = 24; s >= 0; s -= 8) {
        for (int i = tid; i < 256; i += 1024) hist[i] = 0;
        __syncthreads();
        for (int i = tid; i < NGPB; i += 1024) {
            unsigned k = keys[i];
            bool match = (s == 24) || ((k >> (s + 8)) == (prefix >> (s + 8)));
            if (match) atomicAdd(&hist[(k >> s) & 255u], 1);
        }
        __syncthreads();
        if (tid == 0) {
            int gt = 0, c = 255;
            for (; c >= 0; c--) {
                int h = hist[c];
                if (gt + h >= remaining) break;
                gt += h;
            }
            sh_byte = c;
            sh_rem  = remaining - gt;
        }
        __syncthreads();
        prefix |= ((unsigned)sh_byte) << s;
        remaining = sh_rem;
        __syncthreads();
    }
    unsigned thr_key = prefix;

    // feature-wise max over selected nodes of h2[i]*score[i]
    int warp = tid >> 5, lane = tid & 31;
    float m = -FLT_MAX;
    for (int i = warp; i < NGPB; i += 32) {
        if (keys[i] >= thr_key) {
            int v = b*NGPB + i;
            float sc = g_score[v];
            m = fmaxf(m, g_h2[v*32 + lane] * sc);
        }
    }
    red[warp*32 + lane] = m;
    __syncthreads();
    if (tid < G2) {
        float mm = -FLT_MAX;
        #pragma unroll
        for (int w = 0; w < 32; w++) mm = fmaxf(mm, red[w*32 + tid]);
        gvec[tid] = mm;
    }
    __syncthreads();
    if (tid < DENSE) {
        float acc = dense_b[tid];
        #pragma unroll
        for (int k = 0; k < G2; k++) acc += gvec[k]*dense_W[k*DENSE + tid];
        dvec[tid] = fmaxf(acc, 0.f);
    }
    __syncthreads();
    if (tid < NCLS) {
        float acc = out_b[tid];
        #pragma unroll
        for (int k = 0; k < DENSE; k++) acc += dvec[k]*out_W[k*NCLS + tid];
        out[b*NCLS + tid] = acc;
    }
}

// ---------------- launch -----------------------------------------------------
extern "C" void kernel_launch(void* const* d_in, const int* in_sizes, int n_in,
                              void* d_out, int out_size) {
    const int*   x   = (const int*)  d_in[0];
    const int*   ei  = (const int*)  d_in[1];
    const float* emb = (const float*)d_in[3];
    const float* W1  = (const float*)d_in[4];
    const float* b1  = (const float*)d_in[5];
    const float* W2  = (const float*)d_in[6];
    const float* b2  = (const float*)d_in[7];
    const float* pw  = (const float*)d_in[8];
    const float* dW  = (const float*)d_in[9];
    const float* db  = (const float*)d_in[10];
    const float* oW  = (const float*)d_in[11];
    const float* ob  = (const float*)d_in[12];
    float* out = (float*)d_out;

    static int smem_set = 0;
    if (!smem_set) {
        cudaFuncSetAttribute(k_agg<1>, cudaFuncAttributeMaxDynamicSharedMemorySize,
                             AGG_SMEM);
        cudaFuncSetAttribute(k_agg<2>, cudaFuncAttributeMaxDynamicSharedMemorySize,
                             AGG_SMEM);
        smem_set = 1;
    }

    k_embW1 <<<FEAT/8, 256>>>(emb, W1);
    k_build <<<NB*4, 1024>>>(ei, x);
    k_agg<1><<<NB*2, AGG_T, AGG_SMEM>>>(b1, W2, pw);
    k_agg<2><<<NB*2, AGG_T, AGG_SMEM>>>(b2, W2, pw);
    k_topk  <<<NB, 1024>>>(dW, db, oW, ob, out);
}

// round 16
// speedup vs baseline: 1.0427x; 1.0427x over previous
#include <cuda_runtime.h>
#include <cuda_fp16.h>
#include <math.h>
#include <float.h>

#define NB    64
#define NGPB  2000
#define EGPB  64000
#define NN    (NB*NGPB)     // 128000 nodes
#define NE    (NB*EGPB)     // 4096000 edges
#define KSEL  1600
#define EMB   64
#define G1    32
#define G2    32
#define DENSE 64
#define NCLS  10
#define FEAT  10000
#define CAP   80            // padded CSR bucket capacity (deg mean 32, max ~62)
#define QTR   500           // dst nodes owned per build-CTA (4 CTAs per batch)
#define ZROW  NGPB          // local zero-row id (smem row 2000)

// dynamic smem for agg: (NGPB+1) rows x 64 B
#define AGG_SMEM ((NGPB + 1) * 64)

// ---------------- scratch (static device globals; no runtime alloc) ----------
__device__ int     g_cnt[NN];           // per-node in-degree
__device__ float   g_dinv[NN];
__device__ int     g_csrc[NN*CAP];      // padded CSR of LOCAL src ids; pad = ZROW
__device__ float   g_embW1[FEAT*G1];    // emb @ W1  (10000 x 32)
__device__ __half2 g_hs16 [NN*16];      // layer-1 input fp16 (pre-scaled by dinv[src])
__device__ __half2 g_hs216[NN*16];      // layer-2 input fp16 (pre-scaled)
__device__ float   g_h2 [NN*G2];        // final node features (fp32)
__device__ float   g_score[NN];

// ---------------- emb @ W1 (tiny table GEMM) ---------------------------------
__global__ void k_embW1(const float* __restrict__ emb, const float* __restrict__ W1) {
    __shared__ float W1s[EMB*G1];
    for (int i = threadIdx.x; i < EMB*G1; i += blockDim.x) W1s[i] = W1[i];
    __syncthreads();
    int warp = threadIdx.x >> 5, lane = threadIdx.x & 31;
    int r = blockIdx.x*8 + warp;
    if (r >= FEAT) return;
    float e0 = emb[r*EMB + lane];
    float e1 = emb[r*EMB + 32 + lane];
    float acc = 0.f;
    #pragma unroll
    for (int k = 0; k < 32; k++)
        acc += __shfl_sync(0xffffffffu, e0, k) * W1s[k*G1 + lane];
    #pragma unroll
    for (int k = 0; k < 32; k++)
        acc += __shfl_sync(0xffffffffu, e1, k) * W1s[(32+k)*G1 + lane];
    g_embW1[r*G1 + lane] = acc;
}

// ---------------- CSR build: smem counters + direct gmem scatter -------------
// 4 CTAs per batch; CTA owns dst range [b*NGPB + q*QTR, +QTR). Stores LOCAL
// src ids (src - b*NGPB); pad entries = ZROW (smem zero row in agg).
__global__ void __launch_bounds__(1024) k_build(const int* __restrict__ ei,
                                                const int* __restrict__ x) {
    __shared__ int scnt[QTR];
    int b = blockIdx.x >> 2, q = blockIdx.x & 3;
    int tid = threadIdx.x;
    for (int i = tid; i < QTR; i += 1024) scnt[i] = 0;
    __syncthreads();
    int ebase = b*EGPB;
    int bbase = b*NGPB;
    int lo    = bbase + q*QTR;
    const int4* __restrict__ s4 = (const int4*)(ei + ebase);
    const int4* __restrict__ d4 = (const int4*)(ei + NE + ebase);
    for (int t = tid; t < EGPB/4; t += 1024) {
        int4 d = d4[t];
        int4 s = s4[t];
        unsigned r;
        r = (unsigned)(d.x - lo);
        if (r < QTR) g_csrc[d.x*CAP + atomicAdd(&scnt[r], 1)] = s.x - bbase;
        r = (unsigned)(d.y - lo);
        if (r < QTR) g_csrc[d.y*CAP + atomicAdd(&scnt[r], 1)] = s.y - bbase;
        r = (unsigned)(d.z - lo);
        if (r < QTR) g_csrc[d.z*CAP + atomicAdd(&scnt[r], 1)] = s.z - bbase;
        r = (unsigned)(d.w - lo);
        if (r < QTR) g_csrc[d.w*CAP + atomicAdd(&scnt[r], 1)] = s.w - bbase;
    }
    __syncthreads();
    // cnt, dinv, tail pads, hs (fp16) for owned nodes (warp per node)
    int warp = tid >> 5, lane = tid & 31;
    for (int i = warp; i < QTR; i += 32) {
        int v = lo + i;
        int c = scnt[i];
        float dinv = rsqrtf((float)(c + 1));      // +1 self loop
        if (lane == 0) { g_cnt[v] = c; g_dinv[v] = dinv; }
        int padend = ((c + 3) & ~3) + 8;          // covers tail + prefetch quad
        if (padend > CAP) padend = CAP;
        int p = c + lane;
        if (p < padend) g_csrc[v*CAP + p] = ZROW; // max pad span 11 < 32 lanes
        int row = x[v];
        if (lane < 16) {
            float2 e = *(const float2*)&g_embW1[row*32 + 2*lane];
            g_hs16[v*16 + lane] = __floats2half2_rn(e.x*dinv, e.y*dinv);
        }
    }
}

// ---------------- GCN aggregation: SMEM-staged batch block -------------------
// 2 CTAs per batch (128 CTAs, 1024 thr, 1 CTA/SM). Batch feature block
// (2000 x 64 B fp16 rows + zero row) staged in dynamic smem; gathers are
// LDS.128 off local src ids. 4-lane group per dst node; each gathered uint4
// is consumed immediately into fp32 accumulators (register-lean: no fp16
// tree, no spills at the 1024-thread / 64-reg ceiling).
__device__ __forceinline__ __half2 h2u(unsigned u) { return *(__half2*)&u; }

__device__ __forceinline__ void accum8(float* a, uint4 r) {
    float2 t;
    t = __half22float2(h2u(r.x)); a[0] += t.x; a[1] += t.y;
    t = __half22float2(h2u(r.y)); a[2] += t.x; a[3] += t.y;
    t = __half22float2(h2u(r.z)); a[4] += t.x; a[5] += t.y;
    t = __half22float2(h2u(r.w)); a[6] += t.x; a[7] += t.y;
}

template<int MODE>
__global__ void __launch_bounds__(1024) k_agg(const float* __restrict__ bias,
                                              const float* __restrict__ W2,
                                              const float* __restrict__ pw) {
    extern __shared__ uint4 sblk[];         // (NGPB+1) rows x 4 uint4
    __shared__ float W2s[G2*G2];
    int tid = threadIdx.x;
    if (MODE == 1)
        for (int i = tid; i < G2*G2; i += 1024) W2s[i] = W2[i];
    int b = blockIdx.x >> 1, half = blockIdx.x & 1;
    const uint4* __restrict__ gin =
        (const uint4*)((MODE == 1) ? g_hs16 : g_hs216);
    // stage batch block (coalesced) + zero row
    for (int i = tid; i < NGPB*4; i += 1024) sblk[i] = gin[b*NGPB*4 + i];
    if (tid < 4) sblk[NGPB*4 + tid] = make_uint4(0u, 0u, 0u, 0u);
    __syncthreads();

    int lane = tid & 31, warp = tid >> 5;
    int g = lane & 3;                         // lane within 4-lane group
    for (int o = warp; o < 125; o += 32) {    // 125*8 = 1000 nodes per CTA
        int vl = half*1000 + o*8 + (lane >> 2);   // local node id in batch
        int v  = b*NGPB + vl;
        int dg = g_cnt[v];
        float dinv = g_dinv[v];
        const int* __restrict__ bucket = g_csrc + v*CAP;   // local ids

        float a[8] = {0,0,0,0,0,0,0,0};
        accum8(a, sblk[vl*4 + g]);            // self loop
        int4 i4 = *(const int4*)(bucket);     // first index quad
        for (int j = 0; j < dg; j += 4) {     // pads index the zero row
            int4 cur = i4;
            i4 = *(const int4*)(bucket + j + 4);   // prefetch next quad
            uint4 r0 = sblk[cur.x*4 + g];
            uint4 r1 = sblk[cur.y*4 + g];
            uint4 r2 = sblk[cur.z*4 + g];
            uint4 r3 = sblk[cur.w*4 + g];
            accum8(a, r0);
            accum8(a, r1);
            accum8(a, r2);
            accum8(a, r3);
        }
        float4 bs0 = *(const float4*)(bias + g*8);
        float4 bs1 = *(const float4*)(bias + g*8 + 4);
        float vals[8];
        vals[0] = fmaxf(dinv*a[0] + bs0.x, 0.f);
        vals[1] = fmaxf(dinv*a[1] + bs0.y, 0.f);
        vals[2] = fmaxf(dinv*a[2] + bs0.z, 0.f);
        vals[3] = fmaxf(dinv*a[3] + bs0.w, 0.f);
        vals[4] = fmaxf(dinv*a[4] + bs1.x, 0.f);
        vals[5] = fmaxf(dinv*a[5] + bs1.y, 0.f);
        vals[6] = fmaxf(dinv*a[6] + bs1.z, 0.f);
        vals[7] = fmaxf(dinv*a[7] + bs1.w, 0.f);

        if (MODE == 1) {
            // hs2[v][c] = dinv * sum_k val_k W2[k][c], c = g*8..g*8+7 (fp16)
            float acc[8] = {0,0,0,0,0,0,0,0};
            int base = lane & ~3;
            #pragma unroll
            for (int kl = 0; kl < 4; kl++) {
                #pragma unroll
                for (int i = 0; i < 8; i++) {
                    float vx = __shfl_sync(0xffffffffu, vals[i], base + kl);
                    int k = kl*8 + i;
                    float4 w0 = *(const float4*)&W2s[k*G2 + g*8];
                    float4 w1 = *(const float4*)&W2s[k*G2 + g*8 + 4];
                    acc[0] += vx*w0.x; acc[1] += vx*w0.y;
                    acc[2] += vx*w0.z; acc[3] += vx*w0.w;
                    acc[4] += vx*w1.x; acc[5] += vx*w1.y;
                    acc[6] += vx*w1.z; acc[7] += vx*w1.w;
                }
            }
            __half2 h0 = __floats2half2_rn(acc[0]*dinv, acc[1]*dinv);
            __half2 h1 = __floats2half2_rn(acc[2]*dinv, acc[3]*dinv);
            __half2 h2 = __floats2half2_rn(acc[4]*dinv, acc[5]*dinv);
            __half2 h3 = __floats2half2_rn(acc[6]*dinv, acc[7]*dinv);
            uint4 ov;
            ov.x = *(unsigned*)&h0; ov.y = *(unsigned*)&h1;
            ov.z = *(unsigned*)&h2; ov.w = *(unsigned*)&h3;
            ((uint4*)g_hs216)[v*4 + g] = ov;
        } else {
            *(float4*)(g_h2 + v*32 + g*8)     = make_float4(vals[0], vals[1], vals[2], vals[3]);
            *(float4*)(g_h2 + v*32 + g*8 + 4) = make_float4(vals[4], vals[5], vals[6], vals[7]);
            float4 p0 = *(const float4*)(pw + g*8);
            float4 p1 = *(const float4*)(pw + g*8 + 4);
            float dot = vals[0]*p0.x + vals[1]*p0.y + vals[2]*p0.z + vals[3]*p0.w
                      + vals[4]*p1.x + vals[5]*p1.y + vals[6]*p1.z + vals[7]*p1.w;
            float nrm = p0.x*p0.x + p0.y*p0.y + p0.z*p0.z + p0.w*p0.w
                      + p1.x*p1.x + p1.y*p1.y + p1.z*p1.z + p1.w*p1.w;
            #pragma unroll
            for (int o2 = 1; o2 < 4; o2 <<= 1) {
                dot += __shfl_xor_sync(0xffffffffu, dot, o2);
                nrm += __shfl_xor_sync(0xffffffffu, nrm, o2);
            }
            if (g == 0) g_score[v] = tanhf(dot * rsqrtf(nrm));
        }
    }
}

// ---------------- top-k (exact radix select) + pool + dense head -------------
__device__ __forceinline__ unsigned key_flip(unsigned u) {
    return (u & 0x80000000u) ? ~u : (u | 0x80000000u);   // monotone float order
}

__global__ void __launch_bounds__(1024) k_topk(
        const float* __restrict__ dense_W, const float* __restrict__ dense_b,
        const float* __restrict__ out_W,  const float* __restrict__ out_b,
        float* __restrict__ out) {
    __shared__ unsigned keys[NGPB];
    __shared__ int      hist[256];
    __shared__ int      sh_byte, sh_rem;
    __shared__ float    red[32*32];
    __shared__ float    gvec[G2];
    __shared__ float    dvec[DENSE];
    int b = blockIdx.x, tid = threadIdx.x;
    for (int i = tid; i < NGPB; i += 1024)
        keys[i] = key_flip(__float_as_uint(g_score[b*NGPB + i]));
    __syncthreads();

    // exact KSEL-th largest key via 4 byte-wise passes
    unsigned prefix = 0;
    int remaining = KSEL;
    #pragma unroll
    for (int s = 24; s >= 0; s -= 8) {
        for (int i = tid; i < 256; i += 1024) hist[i] = 0;
        __syncthreads();
        for (int i = tid; i < NGPB; i += 1024) {
            unsigned k = keys[i];
            bool match = (s == 24) || ((k >> (s + 8)) == (prefix >> (s + 8)));
            if (match) atomicAdd(&hist[(k >> s) & 255u], 1);
        }
        __syncthreads();
        if (tid == 0) {
            int gt = 0, c = 255;
            for (; c >= 0; c--) {
                int h = hist[c];
                if (gt + h >= remaining) break;
                gt += h;
            }
            sh_byte = c;
            sh_rem  = remaining - gt;
        }
        __syncthreads();
        prefix |= ((unsigned)sh_byte) << s;
        remaining = sh_rem;
        __syncthreads();
    }
    unsigned thr_key = prefix;

    // feature-wise max over selected nodes of h2[i]*score[i]
    int warp = tid >> 5, lane = tid & 31;
    float m = -FLT_MAX;
    for (int i = warp; i < NGPB; i += 32) {
        if (keys[i] >= thr_key) {
            int v = b*NGPB + i;
            float sc = g_score[v];
            m = fmaxf(m, g_h2[v*32 + lane] * sc);
        }
    }
    red[warp*32 + lane] = m;
    __syncthreads();
    if (tid < G2) {
        float mm = -FLT_MAX;
        #pragma unroll
        for (int w = 0; w < 32; w++) mm = fmaxf(mm, red[w*32 + tid]);
        gvec[tid] = mm;
    }
    __syncthreads();
    if (tid < DENSE) {
        float acc = dense_b[tid];
        #pragma unroll
        for (int k = 0; k < G2; k++) acc += gvec[k]*dense_W[k*DENSE + tid];
        dvec[tid] = fmaxf(acc, 0.f);
    }
    __syncthreads();
    if (tid < NCLS) {
        float acc = out_b[tid];
        #pragma unroll
        for (int k = 0; k < DENSE; k++) acc += dvec[k]*out_W[k*NCLS + tid];
        out[b*NCLS + tid] = acc;
    }
}

// ---------------- launch -----------------------------------------------------
extern "C" void kernel_launch(void* const* d_in, const int* in_sizes, int n_in,
                              void* d_out, int out_size) {
    const int*   x   = (const int*)  d_in[0];
    const int*   ei  = (const int*)  d_in[1];
    const float* emb = (const float*)d_in[3];
    const float* W1  = (const float*)d_in[4];
    const float* b1  = (const float*)d_in[5];
    const float* W2  = (const float*)d_in[6];
    const float* b2  = (const float*)d_in[7];
    const float* pw  = (const float*)d_in[8];
    const float* dW  = (const float*)d_in[9];
    const float* db  = (const float*)d_in[10];
    const float* oW  = (const float*)d_in[11];
    const float* ob  = (const float*)d_in[12];
    float* out = (float*)d_out;

    static int smem_set = 0;
    if (!smem_set) {
        cudaFuncSetAttribute(k_agg<1>, cudaFuncAttributeMaxDynamicSharedMemorySize,
                             AGG_SMEM);
        cudaFuncSetAttribute(k_agg<2>, cudaFuncAttributeMaxDynamicSharedMemorySize,
                             AGG_SMEM);
        smem_set = 1;
    }

    k_embW1 <<<FEAT/8, 256>>>(emb, W1);
    k_build <<<NB*4, 1024>>>(ei, x);
    k_agg<1><<<NB*2, 1024, AGG_SMEM>>>(b1, W2, pw);
    k_agg<2><<<NB*2, 1024, AGG_SMEM>>>(b2, W2, pw);
    k_topk  <<<NB, 1024>>>(dW, db, oW, ob, out);
}

// round 17
// speedup vs baseline: 1.0480x; 1.0051x over previous
#include <cuda_runtime.h>
#include <cuda_fp16.h>
#include <math.h>
#include <float.h>

#define NB    64
#define NGPB  2000
#define EGPB  64000
#define NN    (NB*NGPB)     // 128000 nodes
#define NE    (NB*EGPB)     // 4096000 edges
#define KSEL  1600
#define EMB   64
#define G1    32
#define G2    32
#define DENSE 64
#define NCLS  10
#define FEAT  10000
#define CAP   80            // padded CSR bucket capacity (deg mean 32, max ~62)
#define QTR   500           // dst nodes owned per build-CTA (4 CTAs per batch)
#define ZROW  NGPB          // local zero-row id (smem row 2000)

// dynamic smem for agg: (NGPB+1) rows x 64 B
#define AGG_SMEM ((NGPB + 1) * 64)

// ---------------- scratch (static device globals; no runtime alloc) ----------
__device__ int     g_cnt[NN];           // per-node in-degree
__device__ float   g_dinv[NN];
__device__ int     g_csrc[NN*CAP];      // padded CSR of LOCAL src ids; pad = ZROW
__device__ float   g_embW1[FEAT*G1];    // emb @ W1  (10000 x 32)
__device__ __half2 g_hs16 [NN*16];      // layer-1 input fp16 (pre-scaled by dinv[src])
__device__ __half2 g_hs216[NN*16];      // layer-2 input fp16 (pre-scaled)
__device__ float   g_h2 [NN*G2];        // final node features (fp32)
__device__ float   g_score[NN];

// ---------------- emb @ W1 (tiny table GEMM) ---------------------------------
__global__ void k_embW1(const float* __restrict__ emb, const float* __restrict__ W1) {
    __shared__ float W1s[EMB*G1];
    for (int i = threadIdx.x; i < EMB*G1; i += blockDim.x) W1s[i] = W1[i];
    __syncthreads();
    int warp = threadIdx.x >> 5, lane = threadIdx.x & 31;
    int r = blockIdx.x*8 + warp;
    if (r >= FEAT) return;
    float e0 = emb[r*EMB + lane];
    float e1 = emb[r*EMB + 32 + lane];
    float acc = 0.f;
    #pragma unroll
    for (int k = 0; k < 32; k++)
        acc += __shfl_sync(0xffffffffu, e0, k) * W1s[k*G1 + lane];
    #pragma unroll
    for (int k = 0; k < 32; k++)
        acc += __shfl_sync(0xffffffffu, e1, k) * W1s[(32+k)*G1 + lane];
    g_embW1[r*G1 + lane] = acc;
}

// ---------------- CSR build: smem counters + direct gmem scatter -------------
// 4 CTAs per batch; CTA owns dst range [b*NGPB + q*QTR, +QTR). Stores LOCAL
// src ids (src - b*NGPB); pad entries = ZROW (smem zero row in agg).
__global__ void __launch_bounds__(1024) k_build(const int* __restrict__ ei,
                                                const int* __restrict__ x) {
    __shared__ int scnt[QTR];
    int b = blockIdx.x >> 2, q = blockIdx.x & 3;
    int tid = threadIdx.x;
    for (int i = tid; i < QTR; i += 1024) scnt[i] = 0;
    __syncthreads();
    int ebase = b*EGPB;
    int bbase = b*NGPB;
    int lo    = bbase + q*QTR;
    const int4* __restrict__ s4 = (const int4*)(ei + ebase);
    const int4* __restrict__ d4 = (const int4*)(ei + NE + ebase);
    for (int t = tid; t < EGPB/4; t += 1024) {
        int4 d = d4[t];
        int4 s = s4[t];
        unsigned r;
        r = (unsigned)(d.x - lo);
        if (r < QTR) g_csrc[d.x*CAP + atomicAdd(&scnt[r], 1)] = s.x - bbase;
        r = (unsigned)(d.y - lo);
        if (r < QTR) g_csrc[d.y*CAP + atomicAdd(&scnt[r], 1)] = s.y - bbase;
        r = (unsigned)(d.z - lo);
        if (r < QTR) g_csrc[d.z*CAP + atomicAdd(&scnt[r], 1)] = s.z - bbase;
        r = (unsigned)(d.w - lo);
        if (r < QTR) g_csrc[d.w*CAP + atomicAdd(&scnt[r], 1)] = s.w - bbase;
    }
    __syncthreads();
    // cnt, dinv, tail pads, hs (fp16) for owned nodes (warp per node)
    int warp = tid >> 5, lane = tid & 31;
    for (int i = warp; i < QTR; i += 32) {
        int v = lo + i;
        int c = scnt[i];
        float dinv = rsqrtf((float)(c + 1));      // +1 self loop
        if (lane == 0) { g_cnt[v] = c; g_dinv[v] = dinv; }
        int padend = ((c + 3) & ~3) + 8;          // covers tail + prefetch quad
        if (padend > CAP) padend = CAP;
        int p = c + lane;
        if (p < padend) g_csrc[v*CAP + p] = ZROW; // max pad span 11 < 32 lanes
        int row = x[v];
        if (lane < 16) {
            float2 e = *(const float2*)&g_embW1[row*32 + 2*lane];
            g_hs16[v*16 + lane] = __floats2half2_rn(e.x*dinv, e.y*dinv);
        }
    }
}

// ---------------- GCN aggregation: SMEM-staged batch block -------------------
// 2 CTAs per batch (128 CTAs, 1024 thr, 1 CTA/SM). Batch feature block
// (2000 x 64 B fp16 rows + zero row) staged in dynamic smem; gathers are
// LDS.128 off local src ids. 4-lane group per dst node. Inner loop combines
// gathered rows PAIRWISE in fp16 (4 HADD2 per 2 edges, one rounding) and
// promotes immediately to fp32 accumulators: ~10.5 ops/edge, only 2 rows live.
__device__ __forceinline__ __half2 h2u(unsigned u) { return *(__half2*)&u; }

__device__ __forceinline__ void accum8(float* a, uint4 r) {
    float2 t;
    t = __half22float2(h2u(r.x)); a[0] += t.x; a[1] += t.y;
    t = __half22float2(h2u(r.y)); a[2] += t.x; a[3] += t.y;
    t = __half22float2(h2u(r.z)); a[4] += t.x; a[5] += t.y;
    t = __half22float2(h2u(r.w)); a[6] += t.x; a[7] += t.y;
}

// pairwise: promote hadd2(r0,r1) into fp32 accumulators
__device__ __forceinline__ void accum_pair(float* a, uint4 r0, uint4 r1) {
    float2 t;
    t = __half22float2(__hadd2(h2u(r0.x), h2u(r1.x))); a[0] += t.x; a[1] += t.y;
    t = __half22float2(__hadd2(h2u(r0.y), h2u(r1.y))); a[2] += t.x; a[3] += t.y;
    t = __half22float2(__hadd2(h2u(r0.z), h2u(r1.z))); a[4] += t.x; a[5] += t.y;
    t = __half22float2(__hadd2(h2u(r0.w), h2u(r1.w))); a[6] += t.x; a[7] += t.y;
}

template<int MODE>
__global__ void __launch_bounds__(1024) k_agg(const float* __restrict__ bias,
                                              const float* __restrict__ W2,
                                              const float* __restrict__ pw) {
    extern __shared__ uint4 sblk[];         // (NGPB+1) rows x 4 uint4
    __shared__ float W2s[G2*G2];
    int tid = threadIdx.x;
    if (MODE == 1)
        for (int i = tid; i < G2*G2; i += 1024) W2s[i] = W2[i];
    int b = blockIdx.x >> 1, half = blockIdx.x & 1;
    const uint4* __restrict__ gin =
        (const uint4*)((MODE == 1) ? g_hs16 : g_hs216);
    // stage batch block (coalesced) + zero row
    for (int i = tid; i < NGPB*4; i += 1024) sblk[i] = gin[b*NGPB*4 + i];
    if (tid < 4) sblk[NGPB*4 + tid] = make_uint4(0u, 0u, 0u, 0u);
    __syncthreads();

    int lane = tid & 31, warp = tid >> 5;
    int g = lane & 3;                         // lane within 4-lane group
    for (int o = warp; o < 125; o += 32) {    // 125*8 = 1000 nodes per CTA
        int vl = half*1000 + o*8 + (lane >> 2);   // local node id in batch
        int v  = b*NGPB + vl;
        int dg = g_cnt[v];
        float dinv = g_dinv[v];
        const int* __restrict__ bucket = g_csrc + v*CAP;   // local ids

        float a[8] = {0,0,0,0,0,0,0,0};
        accum8(a, sblk[vl*4 + g]);            // self loop (exact fp32 path)
        int4 i4 = *(const int4*)(bucket);     // first index quad
        for (int j = 0; j < dg; j += 4) {     // pads index the zero row
            int4 cur = i4;
            i4 = *(const int4*)(bucket + j + 4);   // prefetch next quad
            uint4 r0 = sblk[cur.x*4 + g];
            uint4 r1 = sblk[cur.y*4 + g];
            accum_pair(a, r0, r1);
            uint4 r2 = sblk[cur.z*4 + g];
            uint4 r3 = sblk[cur.w*4 + g];
            accum_pair(a, r2, r3);
        }
        float4 bs0 = *(const float4*)(bias + g*8);
        float4 bs1 = *(const float4*)(bias + g*8 + 4);
        float vals[8];
        vals[0] = fmaxf(dinv*a[0] + bs0.x, 0.f);
        vals[1] = fmaxf(dinv*a[1] + bs0.y, 0.f);
        vals[2] = fmaxf(dinv*a[2] + bs0.z, 0.f);
        vals[3] = fmaxf(dinv*a[3] + bs0.w, 0.f);
        vals[4] = fmaxf(dinv*a[4] + bs1.x, 0.f);
        vals[5] = fmaxf(dinv*a[5] + bs1.y, 0.f);
        vals[6] = fmaxf(dinv*a[6] + bs1.z, 0.f);
        vals[7] = fmaxf(dinv*a[7] + bs1.w, 0.f);

        if (MODE == 1) {
            // hs2[v][c] = dinv * sum_k val_k W2[k][c], c = g*8..g*8+7 (fp16)
            float acc[8] = {0,0,0,0,0,0,0,0};
            int base = lane & ~3;
            #pragma unroll
            for (int kl = 0; kl < 4; kl++) {
                #pragma unroll
                for (int i = 0; i < 8; i++) {
                    float vx = __shfl_sync(0xffffffffu, vals[i], base + kl);
                    int k = kl*8 + i;
                    float4 w0 = *(const float4*)&W2s[k*G2 + g*8];
                    float4 w1 = *(const float4*)&W2s[k*G2 + g*8 + 4];
                    acc[0] += vx*w0.x; acc[1] += vx*w0.y;
                    acc[2] += vx*w0.z; acc[3] += vx*w0.w;
                    acc[4] += vx*w1.x; acc[5] += vx*w1.y;
                    acc[6] += vx*w1.z; acc[7] += vx*w1.w;
                }
            }
            __half2 h0 = __floats2half2_rn(acc[0]*dinv, acc[1]*dinv);
            __half2 h1 = __floats2half2_rn(acc[2]*dinv, acc[3]*dinv);
            __half2 h2 = __floats2half2_rn(acc[4]*dinv, acc[5]*dinv);
            __half2 h3 = __floats2half2_rn(acc[6]*dinv, acc[7]*dinv);
            uint4 ov;
            ov.x = *(unsigned*)&h0; ov.y = *(unsigned*)&h1;
            ov.z = *(unsigned*)&h2; ov.w = *(unsigned*)&h3;
            ((uint4*)g_hs216)[v*4 + g] = ov;
        } else {
            *(float4*)(g_h2 + v*32 + g*8)     = make_float4(vals[0], vals[1], vals[2], vals[3]);
            *(float4*)(g_h2 + v*32 + g*8 + 4) = make_float4(vals[4], vals[5], vals[6], vals[7]);
            float4 p0 = *(const float4*)(pw + g*8);
            float4 p1 = *(const float4*)(pw + g*8 + 4);
            float dot = vals[0]*p0.x + vals[1]*p0.y + vals[2]*p0.z + vals[3]*p0.w
                      + vals[4]*p1.x + vals[5]*p1.y + vals[6]*p1.z + vals[7]*p1.w;
            float nrm = p0.x*p0.x + p0.y*p0.y + p0.z*p0.z + p0.w*p0.w
                      + p1.x*p1.x + p1.y*p1.y + p1.z*p1.z + p1.w*p1.w;
            #pragma unroll
            for (int o2 = 1; o2 < 4; o2 <<= 1) {
                dot += __shfl_xor_sync(0xffffffffu, dot, o2);
                nrm += __shfl_xor_sync(0xffffffffu, nrm, o2);
            }
            if (g == 0) g_score[v] = tanhf(dot * rsqrtf(nrm));
        }
    }
}

// ---------------- top-k (exact radix select) + pool + dense head -------------
__device__ __forceinline__ unsigned key_flip(unsigned u) {
    return (u & 0x80000000u) ? ~u : (u | 0x80000000u);   // monotone float order
}

__global__ void __launch_bounds__(1024) k_topk(
        const float* __restrict__ dense_W, const float* __restrict__ dense_b,
        const float* __restrict__ out_W,  const float* __restrict__ out_b,
        float* __restrict__ out) {
    __shared__ unsigned keys[NGPB];
    __shared__ int      hist[256];
    __shared__ int      sh_byte, sh_rem;
    __shared__ float    red[32*32];
    __shared__ float    gvec[G2];
    __shared__ float    dvec[DENSE];
    int b = blockIdx.x, tid = threadIdx.x;
    for (int i = tid; i < NGPB; i += 1024)
        keys[i] = key_flip(__float_as_uint(g_score[b*NGPB + i]));
    __syncthreads();

    // exact KSEL-th largest key via 4 byte-wise passes
    unsigned prefix = 0;
    int remaining = KSEL;
    #pragma unroll
    for (int s = 24; s >= 0; s -= 8) {
        for (int i = tid; i < 256; i += 1024) hist[i] = 0;
        __syncthreads();
        for (int i = tid; i < NGPB; i += 1024) {
            unsigned k = keys[i];
            bool match = (s == 24) || ((k >> (s + 8)) == (prefix >> (s + 8)));
            if (match) atomicAdd(&hist[(k >> s) & 255u], 1);
        }
        __syncthreads();
        if (tid == 0) {
            int gt = 0, c = 255;
            for (; c >= 0; c--) {
                int h = hist[c];
                if (gt + h >= remaining) break;
                gt += h;
            }
            sh_byte = c;
            sh_rem  = remaining - gt;
        }
        __syncthreads();
        prefix |= ((unsigned)sh_byte) << s;
        remaining = sh_rem;
        __syncthreads();
    }
    unsigned thr_key = prefix;

    // feature-wise max over selected nodes of h2[i]*score[i]
    int warp = tid >> 5, lane = tid & 31;
    float m = -FLT_MAX;
    for (int i = warp; i < NGPB; i += 32) {
        if (keys[i] >= thr_key) {
            int v = b*NGPB + i;
            float sc = g_score[v];
            m = fmaxf(m, g_h2[v*32 + lane] * sc);
        }
    }
    red[warp*32 + lane] = m;
    __syncthreads();
    if (tid < G2) {
        float mm = -FLT_MAX;
        #pragma unroll
        for (int w = 0; w < 32; w++) mm = fmaxf(mm, red[w*32 + tid]);
        gvec[tid] = mm;
    }
    __syncthreads();
    if (tid < DENSE) {
        float acc = dense_b[tid];
        #pragma unroll
        for (int k = 0; k < G2; k++) acc += gvec[k]*dense_W[k*DENSE + tid];
        dvec[tid] = fmaxf(acc, 0.f);
    }
    __syncthreads();
    if (tid < NCLS) {
        float acc = out_b[tid];
        #pragma unroll
        for (int k = 0; k < DENSE; k++) acc += dvec[k]*out_W[k*NCLS + tid];
        out[b*NCLS + tid] = acc;
    }
}

// ---------------- launch -----------------------------------------------------
extern "C" void kernel_launch(void* const* d_in, const int* in_sizes, int n_in,
                              void* d_out, int out_size) {
    const int*   x   = (const int*)  d_in[0];
    const int*   ei  = (const int*)  d_in[1];
    const float* emb = (const float*)d_in[3];
    const float* W1  = (const float*)d_in[4];
    const float* b1  = (const float*)d_in[5];
    const float* W2  = (const float*)d_in[6];
    const float* b2  = (const float*)d_in[7];
    const float* pw  = (const float*)d_in[8];
    const float* dW  = (const float*)d_in[9];
    const float* db  = (const float*)d_in[10];
    const float* oW  = (const float*)d_in[11];
    const float* ob  = (const float*)d_in[12];
    float* out = (float*)d_out;

    static int smem_set = 0;
    if (!smem_set) {
        cudaFuncSetAttribute(k_agg<1>, cudaFuncAttributeMaxDynamicSharedMemorySize,
                             AGG_SMEM);
        cudaFuncSetAttribute(k_agg<2>, cudaFuncAttributeMaxDynamicSharedMemorySize,
                             AGG_SMEM);
        smem_set = 1;
    }

    k_embW1 <<<FEAT/8, 256>>>(emb, W1);
    k_build <<<NB*4, 1024>>>(ei, x);
    k_agg<1><<<NB*2, 1024, AGG_SMEM>>>(b1, W2, pw);
    k_agg<2><<<NB*2, 1024, AGG_SMEM>>>(b2, W2, pw);
    k_topk  <<<NB, 1024>>>(dW, db, oW, ob, out);
}